// round 3
// baseline (speedup 1.0000x reference)
#include <cuda_runtime.h>
#include <cstdint>

#define NN   100000
#define NNP  100096   // 782 * 128 (padded M)
#define NE   1600000
#define DD   128
#define KK   512      // 3*D (relations) + D (self)
#define LL   3
#define M3   (3 * NN)
#define NB3  ((M3 + 1023) / 1024)   // 293 scan blocks

// ---------------- device scratch (static: no allocation allowed) ----------------
__device__ float    g_h[2][(size_t)NN * DD];     // ping-pong hidden states
__device__ float    g_bt[LL][DD][KK];            // transposed+rna weights: Bt[l][j][k]
__device__ int      g_deg3[M3];
__device__ int      g_off3[M3 + 1];              // CSR offsets keyed by (dst*3 + etype)
__device__ int      g_cur3[M3];
__device__ unsigned g_csr[NE];                   // src node ids, grouped by (dst, etype)
__device__ int      g_bsum[512];

// ---------------- small helpers ----------------
__device__ __forceinline__ uint32_t smem_u32(const void* p) {
    uint32_t a;
    asm("{ .reg .u64 t; cvta.to.shared.u64 t, %1; cvt.u32.u64 %0, t; }" : "=r"(a) : "l"(p));
    return a;
}
__device__ __forceinline__ float rna_tf32(float x) {
    uint32_t u;
    asm("cvt.rna.tf32.f32 %0, %1;" : "=r"(u) : "f"(x));
    return __uint_as_float(u);
}

// ---------------- CSR construction: key = dst*3 + etype ----------------
__global__ void k_zero_deg() {
    int i = blockIdx.x * 256 + threadIdx.x;
    if (i < M3) g_deg3[i] = 0;
}
__global__ void k_hist(const int* __restrict__ dst, const int* __restrict__ ety) {
    int e = blockIdx.x * 256 + threadIdx.x;
    if (e < NE) atomicAdd(&g_deg3[dst[e] * 3 + ety[e]], 1);
}
__global__ void k_scan1() {
    __shared__ int s[1024];
    int t = threadIdx.x;
    int i = blockIdx.x * 1024 + t;
    int v = (i < M3) ? g_deg3[i] : 0;
    s[t] = v;
    __syncthreads();
    #pragma unroll
    for (int d = 1; d < 1024; d <<= 1) {
        int x = (t >= d) ? s[t - d] : 0;
        __syncthreads();
        s[t] += x;
        __syncthreads();
    }
    if (i < M3) g_off3[i + 1] = s[t];
    if (t == 1023) g_bsum[blockIdx.x] = s[1023];
}
__global__ void k_scan2() {   // 1 block, 512 threads: exclusive scan of NB3 block sums
    __shared__ int s[512];
    int t = threadIdx.x;
    int v = (t < NB3) ? g_bsum[t] : 0;
    s[t] = v;
    __syncthreads();
    #pragma unroll
    for (int d = 1; d < 512; d <<= 1) {
        int x = (t >= d) ? s[t - d] : 0;
        __syncthreads();
        s[t] += x;
        __syncthreads();
    }
    if (t < NB3) g_bsum[t] = s[t] - v;
}
__global__ void k_scan3() {
    int t = threadIdx.x;
    int i = blockIdx.x * 1024 + t;
    if (i < M3) g_off3[i + 1] += g_bsum[blockIdx.x];
    if (i == 0) g_off3[0] = 0;
}
__global__ void k_cursor() {
    int i = blockIdx.x * 256 + threadIdx.x;
    if (i < M3) g_cur3[i] = g_off3[i];
}
__global__ void k_scatter(const int* __restrict__ src, const int* __restrict__ dst,
                          const int* __restrict__ ety) {
    int e = blockIdx.x * 256 + threadIdx.x;
    if (e < NE) {
        int key = dst[e] * 3 + ety[e];
        int pos = atomicAdd(&g_cur3[key], 1);
        g_csr[pos] = (unsigned)src[e];
    }
}

// ---------------- weight transpose + tf32 rounding ----------------
// Bt[l][j][k] : k<384 -> W[l][k>>7][k&127][j],  k>=384 -> W_self[l][k-384][j]
__global__ void k_wt(const float* __restrict__ W, const float* __restrict__ Ws) {
    int idx = blockIdx.x * 256 + threadIdx.x;
    if (idx < LL * DD * KK) {
        int l = idx / (DD * KK);
        int rem = idx % (DD * KK);
        int j = rem / KK;
        int k = rem % KK;
        float v = (k < 384)
            ? W[(((size_t)l * 3 + (k >> 7)) * DD + (k & 127)) * DD + j]
            : Ws[((size_t)l * DD + (k - 384)) * DD + j];
        (&g_bt[0][0][0])[idx] = rna_tf32(v);
    }
}

// ---------------- fused aggregate + GEMM kernel ----------------
// 512 threads: warps 0-7 produce A slices (per-relation aggregation -> smem),
// warps 8-15 consume via mma.sync tf32, streaming B with a 4-deep cp.async ring.
static constexpr int A_PAD    = 132;                 // 128 + 4 (conflict-free frags)
static constexpr int B_PAD    = 36;                  // 32 + 4
static constexpr int A_TILE   = 128 * A_PAD;         // floats per A buffer
static constexpr int B_STAGE  = 128 * B_PAD;         // floats per B ring stage
static constexpr int SM_FLTS  = 2 * A_TILE + 4 * B_STAGE;
static constexpr int FUSE_SMEM = SM_FLTS * 4;        // 208896 bytes

__device__ __forceinline__ void mma_tf32_16x8x8(float c[4],
                                                uint32_t a0, uint32_t a1, uint32_t a2, uint32_t a3,
                                                uint32_t b0, uint32_t b1) {
    asm volatile(
        "mma.sync.aligned.m16n8k8.row.col.f32.tf32.tf32.f32 "
        "{%0,%1,%2,%3}, {%4,%5,%6,%7}, {%8,%9}, {%0,%1,%2,%3};"
        : "+f"(c[0]), "+f"(c[1]), "+f"(c[2]), "+f"(c[3])
        : "r"(a0), "r"(a1), "r"(a2), "r"(a3), "r"(b0), "r"(b1));
}

__device__ __forceinline__ void load_B_chunk(const float* __restrict__ B, uint32_t BbA,
                                             int c, int ctid) {
    uint32_t sB = BbA + (uint32_t)((c & 3) * B_STAGE) * 4u;
    #pragma unroll
    for (int i = 0; i < 4; i++) {
        int u = ctid + i * 256;
        int rr = u >> 3, cl = u & 7;
        const float* gsrc = B + (size_t)rr * KK + c * 32 + cl * 4;
        uint32_t d = sB + (uint32_t)(rr * B_PAD + cl * 4) * 4u;
        asm volatile("cp.async.cg.shared.global [%0], [%1], 16;" :: "r"(d), "l"(gsrc));
    }
    asm volatile("cp.async.commit_group;" ::: "memory");
}

// producers: aggregate relation slice r (r==3 -> self h) for 128-node tile into Abuf
__device__ __forceinline__ void agg_slice(const float4* __restrict__ h4, size_t row0,
                                          int r, float* __restrict__ Abuf,
                                          int pw, int lane) {
    #pragma unroll 1
    for (int i = 0; i < 16; i++) {
        int row = pw * 16 + i;
        size_t node = row0 + (size_t)row;
        float4 a = {0.f, 0.f, 0.f, 0.f};
        if (node < NN) {
            if (r < 3) {
                int e0 = __ldg(&g_off3[node * 3 + r]);
                int e1 = __ldg(&g_off3[node * 3 + r + 1]);
                float4 b = {0.f, 0.f, 0.f, 0.f};
                int e = e0;
                for (; e + 3 < e1; e += 4) {
                    unsigned s0 = __ldg(&g_csr[e]);
                    unsigned s1 = __ldg(&g_csr[e + 1]);
                    unsigned s2 = __ldg(&g_csr[e + 2]);
                    unsigned s3 = __ldg(&g_csr[e + 3]);
                    float4 v0 = __ldg(&h4[(size_t)s0 * 32 + lane]);
                    float4 v1 = __ldg(&h4[(size_t)s1 * 32 + lane]);
                    float4 v2 = __ldg(&h4[(size_t)s2 * 32 + lane]);
                    float4 v3 = __ldg(&h4[(size_t)s3 * 32 + lane]);
                    a.x += v0.x + v2.x; a.y += v0.y + v2.y;
                    a.z += v0.z + v2.z; a.w += v0.w + v2.w;
                    b.x += v1.x + v3.x; b.y += v1.y + v3.y;
                    b.z += v1.z + v3.z; b.w += v1.w + v3.w;
                }
                for (; e < e1; e++) {
                    unsigned s0 = __ldg(&g_csr[e]);
                    float4 v0 = __ldg(&h4[(size_t)s0 * 32 + lane]);
                    a.x += v0.x; a.y += v0.y; a.z += v0.z; a.w += v0.w;
                }
                a.x += b.x; a.y += b.y; a.z += b.z; a.w += b.w;
            } else {
                a = __ldg(&h4[node * 32 + lane]);
            }
        }
        float4 rv;
        rv.x = rna_tf32(a.x); rv.y = rna_tf32(a.y);
        rv.z = rna_tf32(a.z); rv.w = rna_tf32(a.w);
        *reinterpret_cast<float4*>(Abuf + (size_t)row * A_PAD + lane * 4) = rv;
    }
}

__global__ void __launch_bounds__(512, 1)
k_fused(const float4* __restrict__ h4, int layer, const float* __restrict__ bias,
        float* __restrict__ hout) {
    extern __shared__ float sm[];
    float* Ab0 = sm;
    float* Ab1 = sm + A_TILE;
    float* Bb  = sm + 2 * A_TILE;
    uint32_t BbA = smem_u32(Bb);

    int tid = threadIdx.x, wid = tid >> 5, lane = tid & 31;
    size_t row0 = (size_t)blockIdx.x * 128;
    const float* B = &g_bt[layer][0][0];
    bool producer = (wid < 8);

    // consumer accumulators (producers never touch them)
    float acc[2][8][4];
    #pragma unroll
    for (int mt = 0; mt < 2; mt++)
        #pragma unroll
        for (int nt = 0; nt < 8; nt++)
            #pragma unroll
            for (int v = 0; v < 4; v++) acc[mt][nt][v] = 0.0f;

    int ctid = tid - 256;
    int wid8 = wid - 8;
    int warp_m = wid8 >> 1, warp_n = wid8 & 1;
    int g = lane >> 2, q = lane & 3;

    if (producer) {
        agg_slice(h4, row0, 0, Ab0, wid, lane);
    } else {
        #pragma unroll
        for (int c = 0; c < 3; c++) load_B_chunk(B, BbA, c, ctid);
    }
    __syncthreads();

    #pragma unroll 1
    for (int r = 0; r < 4; r++) {
        if (producer) {
            if (r < 3) agg_slice(h4, row0, r + 1, (r & 1) ? Ab0 : Ab1, wid, lane);
        } else {
            const uint32_t* tA = reinterpret_cast<const uint32_t*>((r & 1) ? Ab1 : Ab0);
            #pragma unroll
            for (int j = 0; j < 4; j++) {
                int c = r * 4 + j;
                if (c < 13) asm volatile("cp.async.wait_group 2;" ::: "memory");
                else        asm volatile("cp.async.wait_group 0;" ::: "memory");
                asm volatile("bar.sync 1, 256;" ::: "memory");
                if (c + 3 < 16) load_B_chunk(B, BbA, c + 3, ctid);
                const uint32_t* tB = reinterpret_cast<const uint32_t*>(Bb + (c & 3) * B_STAGE);

                #pragma unroll
                for (int k8 = 0; k8 < 4; k8++) {
                    int k0A = j * 32 + k8 * 8;
                    int k0B = k8 * 8;
                    uint32_t af[2][4];
                    #pragma unroll
                    for (int mt = 0; mt < 2; mt++) {
                        int rb = warp_m * 32 + mt * 16;
                        af[mt][0] = tA[(rb + g)     * A_PAD + k0A + q];
                        af[mt][1] = tA[(rb + g + 8) * A_PAD + k0A + q];
                        af[mt][2] = tA[(rb + g)     * A_PAD + k0A + q + 4];
                        af[mt][3] = tA[(rb + g + 8) * A_PAD + k0A + q + 4];
                    }
                    #pragma unroll
                    for (int nt = 0; nt < 8; nt++) {
                        int nb = warp_n * 64 + nt * 8;
                        uint32_t b0 = tB[(nb + g) * B_PAD + k0B + q];
                        uint32_t b1 = tB[(nb + g) * B_PAD + k0B + q + 4];
                        mma_tf32_16x8x8(acc[0][nt], af[0][0], af[0][1], af[0][2], af[0][3], b0, b1);
                        mma_tf32_16x8x8(acc[1][nt], af[1][0], af[1][1], af[1][2], af[1][3], b0, b1);
                    }
                }
                asm volatile("bar.sync 1, 256;" ::: "memory");
            }
        }
        __syncthreads();
    }

    // epilogue (consumers only)
    if (!producer) {
        #pragma unroll
        for (int mt = 0; mt < 2; mt++) {
            size_t r0 = row0 + (size_t)(warp_m * 32 + mt * 16 + g);
            size_t r1 = r0 + 8;
            #pragma unroll
            for (int nt = 0; nt < 8; nt++) {
                int cb = warp_n * 64 + nt * 8 + q * 2;
                float bz0 = __ldg(&bias[cb]), bz1 = __ldg(&bias[cb + 1]);
                if (r0 < NN) {
                    hout[r0 * DD + cb]     = acc[mt][nt][0] + bz0;
                    hout[r0 * DD + cb + 1] = acc[mt][nt][1] + bz1;
                }
                if (r1 < NN) {
                    hout[r1 * DD + cb]     = acc[mt][nt][2] + bz0;
                    hout[r1 * DD + cb + 1] = acc[mt][nt][3] + bz1;
                }
            }
        }
    }
}

// ---------------- launch ----------------
extern "C" void kernel_launch(void* const* d_in, const int* in_sizes, int n_in,
                              void* d_out, int out_size) {
    const float* feat = (const float*)d_in[0];
    const float* W    = (const float*)d_in[1];
    const float* Ws   = (const float*)d_in[2];
    const float* bias = (const float*)d_in[3];
    const int*   src  = (const int*)d_in[4];
    const int*   dst  = (const int*)d_in[5];
    const int*   ety  = (const int*)d_in[6];
    float*       out  = (float*)d_out;

    cudaFuncSetAttribute(k_fused, cudaFuncAttributeMaxDynamicSharedMemorySize, FUSE_SMEM);

    void* hsym = nullptr;
    cudaGetSymbolAddress(&hsym, g_h);
    float* h0 = (float*)hsym;
    float* h1 = h0 + (size_t)NN * DD;

    // CSR by (dst, etype) — graph fixed across layers, build once per launch
    k_zero_deg<<<(M3 + 255) / 256, 256>>>();
    k_hist<<<(NE + 255) / 256, 256>>>(dst, ety);
    k_scan1<<<NB3, 1024>>>();
    k_scan2<<<1, 512>>>();
    k_scan3<<<NB3, 1024>>>();
    k_cursor<<<(M3 + 255) / 256, 256>>>();
    k_scatter<<<(NE + 255) / 256, 256>>>(src, dst, ety);
    k_wt<<<(LL * DD * KK + 255) / 256, 256>>>(W, Ws);

    const float* hin = feat;
    for (int l = 0; l < LL; l++) {
        float* ho = (l == 2) ? out : (l == 0 ? h0 : h1);
        k_fused<<<NNP / 128, 512, FUSE_SMEM>>>((const float4*)hin, l, bias + l * DD, ho);
        hin = ho;
    }
}

// round 4
// speedup vs baseline: 2.1783x; 2.1783x over previous
#include <cuda_runtime.h>
#include <cstdint>

#define NN   100000
#define NNP  100096   // 782 * 128 (padded M)
#define NE   1600000
#define DD   128
#define KK   512      // 3*D (relations) + D (self)
#define LL   3

// ---------------- device scratch (static: no allocation allowed) ----------------
__device__ float    g_agg[(size_t)NNP * KK];     // [node][512]: rel0|rel1|rel2|rna(h)
__device__ float    g_h[2][(size_t)NN * DD];     // ping-pong hidden states
__device__ float    g_bt[LL][DD][KK];            // transposed+rna weights: Bt[l][j][k]
__device__ int      g_deg[NN];
__device__ int      g_off[NN + 1];
__device__ int      g_cur[NN];
__device__ unsigned g_csr[NE];                   // src | (etype<<20)
__device__ int      g_bsum[128];

// ---------------- small helpers ----------------
__device__ __forceinline__ uint32_t smem_u32(const void* p) {
    uint32_t a;
    asm("{ .reg .u64 t; cvta.to.shared.u64 t, %1; cvt.u32.u64 %0, t; }" : "=r"(a) : "l"(p));
    return a;
}
__device__ __forceinline__ float rna_tf32(float x) {
    uint32_t u;
    asm("cvt.rna.tf32.f32 %0, %1;" : "=r"(u) : "f"(x));
    return __uint_as_float(u);
}

// ---------------- CSR construction (key = dst, etype packed in csr entry) -------
__global__ void k_zero_deg() {
    int i = blockIdx.x * 256 + threadIdx.x;
    if (i < NN) g_deg[i] = 0;
}
__global__ void k_hist(const int* __restrict__ dst) {
    int e = blockIdx.x * 256 + threadIdx.x;
    if (e < NE) atomicAdd(&g_deg[__ldg(&dst[e])], 1);
}
__global__ void k_scan1() {
    __shared__ int s[1024];
    int t = threadIdx.x;
    int i = blockIdx.x * 1024 + t;
    int v = (i < NN) ? g_deg[i] : 0;
    s[t] = v;
    __syncthreads();
    #pragma unroll
    for (int d = 1; d < 1024; d <<= 1) {
        int x = (t >= d) ? s[t - d] : 0;
        __syncthreads();
        s[t] += x;
        __syncthreads();
    }
    if (i < NN) g_off[i + 1] = s[t];
    if (t == 1023) g_bsum[blockIdx.x] = s[1023];
}
__global__ void k_scan2() {
    if (threadIdx.x == 0) {
        int run = 0;
        for (int b = 0; b < 98; b++) { int x = g_bsum[b]; g_bsum[b] = run; run += x; }
    }
}
__global__ void k_scan3() {   // finalize offsets AND write cursors (merged k_cursor)
    int t = threadIdx.x;
    int i = blockIdx.x * 1024 + t;
    if (i < NN) {
        int v = g_off[i + 1] + g_bsum[blockIdx.x];
        g_off[i + 1] = v;
        g_cur[i + 1] = v;        // cursor for node i+1
    }
    if (i == 0) { g_off[0] = 0; g_cur[0] = 0; }
}
__global__ void k_scatter(const int* __restrict__ src, const int* __restrict__ dst,
                          const int* __restrict__ ety) {
    int e = blockIdx.x * 256 + threadIdx.x;
    if (e < NE) {
        int d = __ldg(&dst[e]);
        int pos = atomicAdd(&g_cur[d], 1);
        g_csr[pos] = (unsigned)__ldg(&src[e]) | ((unsigned)__ldg(&ety[e]) << 20);
    }
}

// ---------------- weight transpose + tf32 rounding ----------------
// Bt[l][j][k] : k<384 -> W[l][k>>7][k&127][j],  k>=384 -> W_self[l][k-384][j]
__global__ void k_wt(const float* __restrict__ W, const float* __restrict__ Ws) {
    int idx = blockIdx.x * 256 + threadIdx.x;
    if (idx < LL * DD * KK) {
        int l = idx / (DD * KK);
        int rem = idx % (DD * KK);
        int j = rem / KK;
        int k = rem % KK;
        float v = (k < 384)
            ? W[(((size_t)l * 3 + (k >> 7)) * DD + (k & 127)) * DD + j]
            : Ws[((size_t)l * DD + (k - 384)) * DD + j];
        (&g_bt[0][0][0])[idx] = rna_tf32(v);
    }
}

// ---------------- per-relation aggregation (one warp per node, no atomics) ------
// g_agg stores are evict-first (__stcs): streamed once, must not evict h from L2.
__global__ void __launch_bounds__(256) k_agg(const float4* __restrict__ h4) {
    int gw = (blockIdx.x * blockDim.x + threadIdx.x) >> 5;
    int lane = threadIdx.x & 31;
    if (gw >= NN) return;
    int e0 = g_off[gw], e1 = g_off[gw + 1];
    float4 a0 = {0, 0, 0, 0}, a1 = {0, 0, 0, 0}, a2 = {0, 0, 0, 0};

    auto acc = [&](unsigned t, const float4& v) {
        if (t == 0)      { a0.x += v.x; a0.y += v.y; a0.z += v.z; a0.w += v.w; }
        else if (t == 1) { a1.x += v.x; a1.y += v.y; a1.z += v.z; a1.w += v.w; }
        else             { a2.x += v.x; a2.y += v.y; a2.z += v.z; a2.w += v.w; }
    };

    int e = e0;
    for (; e + 3 < e1; e += 4) {          // unroll 4: MLP 4 per warp
        unsigned p0 = __ldcs(&g_csr[e]);
        unsigned p1 = __ldcs(&g_csr[e + 1]);
        unsigned p2 = __ldcs(&g_csr[e + 2]);
        unsigned p3 = __ldcs(&g_csr[e + 3]);
        float4 v0 = __ldg(&h4[(size_t)(p0 & 0xFFFFFu) * 32 + lane]);
        float4 v1 = __ldg(&h4[(size_t)(p1 & 0xFFFFFu) * 32 + lane]);
        float4 v2 = __ldg(&h4[(size_t)(p2 & 0xFFFFFu) * 32 + lane]);
        float4 v3 = __ldg(&h4[(size_t)(p3 & 0xFFFFFu) * 32 + lane]);
        acc(p0 >> 20, v0);
        acc(p1 >> 20, v1);
        acc(p2 >> 20, v2);
        acc(p3 >> 20, v3);
    }
    for (; e < e1; e++) {
        unsigned p0 = __ldcs(&g_csr[e]);
        float4 v0 = __ldg(&h4[(size_t)(p0 & 0xFFFFFu) * 32 + lane]);
        acc(p0 >> 20, v0);
    }

    float4 s3 = __ldg(&h4[(size_t)gw * 32 + lane]);
    auto rna4 = [](float4 v) {
        float4 r;
        r.x = rna_tf32(v.x); r.y = rna_tf32(v.y); r.z = rna_tf32(v.z); r.w = rna_tf32(v.w);
        return r;
    };
    float4* o = reinterpret_cast<float4*>(g_agg) + (size_t)gw * 128;
    __stcs(&o[lane],      rna4(a0));
    __stcs(&o[32 + lane], rna4(a1));
    __stcs(&o[64 + lane], rna4(a2));
    __stcs(&o[96 + lane], rna4(s3));
}

// ---------------- mma.sync tf32 GEMM: [NNP x 512] @ Bt[l]^T -> [NNP x 128] ------
// CTA tile 128x128, K=512 in 16 chunks of 32. 8 warps: 4(m) x 2(n), warp tile 32x64.
// 3-stage cp.async ring (2 in flight) -> 108KB smem -> 2 CTAs/SM.
// A reads carry an L2 evict-first policy (single-use stream; protect h residency).
static constexpr int GM_STAGES  = 3;
static constexpr int ROW_PAD    = 36;                      // 32 + 4
static constexpr int TILE_FLTS  = 128 * ROW_PAD;           // per operand per stage
static constexpr int STAGE_FLTS = 2 * TILE_FLTS;           // A + B
static constexpr int GEMM_SMEM  = GM_STAGES * STAGE_FLTS * 4;  // 110592 bytes

__device__ __forceinline__ void mma_tf32_16x8x8(float c[4],
                                                uint32_t a0, uint32_t a1, uint32_t a2, uint32_t a3,
                                                uint32_t b0, uint32_t b1) {
    asm volatile(
        "mma.sync.aligned.m16n8k8.row.col.f32.tf32.tf32.f32 "
        "{%0,%1,%2,%3}, {%4,%5,%6,%7}, {%8,%9}, {%0,%1,%2,%3};"
        : "+f"(c[0]), "+f"(c[1]), "+f"(c[2]), "+f"(c[3])
        : "r"(a0), "r"(a1), "r"(a2), "r"(a3), "r"(b0), "r"(b1));
}

__global__ void __launch_bounds__(256, 2)
k_gemm(int layer, const float* __restrict__ bias, float* __restrict__ hout) {
    extern __shared__ float sm[];
    uint32_t smaddr = smem_u32(sm);

    int tid = threadIdx.x, wid = tid >> 5, lane = tid & 31;
    int warp_m = wid >> 1, warp_n = wid & 1;
    int g = lane >> 2, q = lane & 3;

    const float* A = g_agg;
    const float* B = &g_bt[layer][0][0];
    size_t row0 = (size_t)blockIdx.x * 128;

    uint64_t pol;
    asm volatile("createpolicy.fractional.L2::evict_first.b64 %0;" : "=l"(pol));

    int r_ld[4], c_ld[4];
    #pragma unroll
    for (int i = 0; i < 4; i++) {
        int u = tid + i * 256;
        r_ld[i] = u >> 3;
        c_ld[i] = u & 7;
    }

    auto load_chunk = [&](int kc) {
        int st = kc % GM_STAGES;
        uint32_t sA = smaddr + (uint32_t)(st * STAGE_FLTS) * 4u;
        uint32_t sB = sA + (uint32_t)TILE_FLTS * 4u;
        #pragma unroll
        for (int i = 0; i < 4; i++) {
            const float* gsrc = A + (row0 + (size_t)r_ld[i]) * KK + kc * 32 + c_ld[i] * 4;
            uint32_t d = sA + (uint32_t)(r_ld[i] * ROW_PAD + c_ld[i] * 4) * 4u;
            asm volatile("cp.async.cg.shared.global.L2::cache_hint [%0], [%1], 16, %2;"
                         :: "r"(d), "l"(gsrc), "l"(pol));
        }
        #pragma unroll
        for (int i = 0; i < 4; i++) {
            const float* gsrc = B + (size_t)r_ld[i] * KK + kc * 32 + c_ld[i] * 4;
            uint32_t d = sB + (uint32_t)(r_ld[i] * ROW_PAD + c_ld[i] * 4) * 4u;
            asm volatile("cp.async.cg.shared.global [%0], [%1], 16;" :: "r"(d), "l"(gsrc));
        }
        asm volatile("cp.async.commit_group;" ::: "memory");
    };

    float acc[2][8][4];
    #pragma unroll
    for (int mt = 0; mt < 2; mt++)
        #pragma unroll
        for (int nt = 0; nt < 8; nt++)
            #pragma unroll
            for (int v = 0; v < 4; v++) acc[mt][nt][v] = 0.0f;

    // prologue: 2 chunks in flight
    load_chunk(0);
    load_chunk(1);

    const uint32_t* smu = reinterpret_cast<const uint32_t*>(sm);

    #pragma unroll
    for (int kc = 0; kc < 16; kc++) {
        if (kc < 14) asm volatile("cp.async.wait_group 1;" ::: "memory");
        else         asm volatile("cp.async.wait_group 0;" ::: "memory");
        __syncthreads();

        if (kc + 2 < 16) load_chunk(kc + 2);

        int st = kc % GM_STAGES;
        const uint32_t* tA = smu + st * STAGE_FLTS;
        const uint32_t* tB = tA + TILE_FLTS;

        #pragma unroll
        for (int k8 = 0; k8 < 4; k8++) {
            int k0 = k8 * 8;
            uint32_t af[2][4];
            #pragma unroll
            for (int mt = 0; mt < 2; mt++) {
                int rb = warp_m * 32 + mt * 16;
                af[mt][0] = tA[(rb + g)     * ROW_PAD + k0 + q];
                af[mt][1] = tA[(rb + g + 8) * ROW_PAD + k0 + q];
                af[mt][2] = tA[(rb + g)     * ROW_PAD + k0 + q + 4];
                af[mt][3] = tA[(rb + g + 8) * ROW_PAD + k0 + q + 4];
            }
            #pragma unroll
            for (int nt = 0; nt < 8; nt++) {
                int nb = warp_n * 64 + nt * 8;
                uint32_t b0 = tB[(nb + g) * ROW_PAD + k0 + q];
                uint32_t b1 = tB[(nb + g) * ROW_PAD + k0 + q + 4];
                mma_tf32_16x8x8(acc[0][nt], af[0][0], af[0][1], af[0][2], af[0][3], b0, b1);
                mma_tf32_16x8x8(acc[1][nt], af[1][0], af[1][1], af[1][2], af[1][3], b0, b1);
            }
        }
        __syncthreads();
    }

    // epilogue
    #pragma unroll
    for (int mt = 0; mt < 2; mt++) {
        size_t r0 = row0 + (size_t)(warp_m * 32 + mt * 16 + g);
        size_t r1 = r0 + 8;
        #pragma unroll
        for (int nt = 0; nt < 8; nt++) {
            int cb = warp_n * 64 + nt * 8 + q * 2;
            float bz0 = __ldg(&bias[cb]), bz1 = __ldg(&bias[cb + 1]);
            if (r0 < NN) {
                hout[r0 * DD + cb]     = acc[mt][nt][0] + bz0;
                hout[r0 * DD + cb + 1] = acc[mt][nt][1] + bz1;
            }
            if (r1 < NN) {
                hout[r1 * DD + cb]     = acc[mt][nt][2] + bz0;
                hout[r1 * DD + cb + 1] = acc[mt][nt][3] + bz1;
            }
        }
    }
}

// ---------------- launch ----------------
extern "C" void kernel_launch(void* const* d_in, const int* in_sizes, int n_in,
                              void* d_out, int out_size) {
    const float* feat = (const float*)d_in[0];
    const float* W    = (const float*)d_in[1];
    const float* Ws   = (const float*)d_in[2];
    const float* bias = (const float*)d_in[3];
    const int*   src  = (const int*)d_in[4];
    const int*   dst  = (const int*)d_in[5];
    const int*   ety  = (const int*)d_in[6];
    float*       out  = (float*)d_out;

    static int smem_set = 0;
    if (!smem_set) {
        cudaFuncSetAttribute(k_gemm, cudaFuncAttributeMaxDynamicSharedMemorySize, GEMM_SMEM);
        smem_set = 1;
    }

    void* hsym = nullptr;
    cudaGetSymbolAddress(&hsym, g_h);
    float* h0 = (float*)hsym;
    float* h1 = h0 + (size_t)NN * DD;

    // CSR by dst (graph fixed across layers -> build once per launch)
    k_zero_deg<<<(NN + 255) / 256, 256>>>();
    k_hist<<<(NE + 255) / 256, 256>>>(dst);
    k_scan1<<<98, 1024>>>();
    k_scan2<<<1, 32>>>();
    k_scan3<<<98, 1024>>>();           // also writes cursors
    k_scatter<<<(NE + 255) / 256, 256>>>(src, dst, ety);
    k_wt<<<(LL * DD * KK + 255) / 256, 256>>>(W, Ws);

    const float* hin = feat;
    for (int l = 0; l < LL; l++) {
        k_agg<<<(NN * 32 + 255) / 256, 256>>>((const float4*)hin);
        float* ho = (l == 2) ? out : (l == 0 ? h0 : h1);
        k_gemm<<<782, 256, GEMM_SMEM>>>(l, bias + l * DD, ho);
        hin = ho;
    }
}